// round 3
// baseline (speedup 1.0000x reference)
#include <cuda_runtime.h>

#define BSZ 4096
#define TSZ 4096

// per-element loss partials
__device__ double g_loss_partial[BSZ];
// staging buffers, [T][B] layout for coalesced per-step access
__device__ float g_xT[(long)TSZ * BSZ];
__device__ float g_oT[(long)TSZ * BSZ];

__device__ __forceinline__ float tanhx(float x) {
    float y; asm("tanh.approx.f32 %0, %1;" : "=f"(y) : "f"(x)); return y;
}
// sigmoid with pre-halved argument: sig(a) = 0.5*tanh(a/2)+0.5; caller passes a/2
__device__ __forceinline__ float sig_h(float ah) { return fmaf(0.5f, tanhx(ah), 0.5f); }

// One thread per batch element. Encoder (masked) then autoregressive decoder.
__global__ void __launch_bounds__(32, 1) gru_kernel(
    const int* __restrict__ lens,
    const float* __restrict__ eWih, const float* __restrict__ eWhh,
    const float* __restrict__ ebih, const float* __restrict__ ebhh,
    const float* __restrict__ dWih, const float* __restrict__ dWhh,
    const float* __restrict__ dbih, const float* __restrict__ dbhh,
    const float* __restrict__ linW, const float* __restrict__ linb)
{
    const int b   = blockIdx.x * 32 + threadIdx.x;
    const int len = lens[b];

    // ---------------- encoder weights (r,z rows pre-halved for sigmoid) ----------
    float wi[6], wh[6][3], bs[6];
#pragma unroll
    for (int j = 0; j < 6; j++) {
        wi[j] = 0.5f * eWih[j];
        bs[j] = 0.5f * (ebih[j] + ebhh[j]);
#pragma unroll
        for (int k = 0; k < 3; k++) wh[j][k] = 0.5f * eWhh[j * 3 + k];
    }
    float win[3], bin_[3], whn[3][3], bhn[3];
#pragma unroll
    for (int j = 0; j < 3; j++) {
        win[j]  = eWih[6 + j];
        bin_[j] = ebih[6 + j];
        bhn[j]  = ebhh[6 + j];
#pragma unroll
        for (int k = 0; k < 3; k++) whn[j][k] = eWhh[(6 + j) * 3 + k];
    }

    float h0 = 0.f, h1 = 0.f, h2 = 0.f;
    const int wmax = __reduce_max_sync(0xFFFFFFFFu, len);

    // ---------------- encoder loop ----------------
#pragma unroll 4
    for (int t = 0; t < wmax; t++) {
        float xv = g_xT[(long)t * BSZ + b];
        float a[6];
#pragma unroll
        for (int j = 0; j < 6; j++)
            a[j] = fmaf(h2, wh[j][2], fmaf(h1, wh[j][1], fmaf(h0, wh[j][0], fmaf(xv, wi[j], bs[j]))));
        float r0 = sig_h(a[0]), r1 = sig_h(a[1]), r2 = sig_h(a[2]);
        float z0 = sig_h(a[3]), z1 = sig_h(a[4]), z2 = sig_h(a[5]);

        float n0, n1, n2;
        {
            float hn0 = fmaf(h2, whn[0][2], fmaf(h1, whn[0][1], fmaf(h0, whn[0][0], bhn[0])));
            float hn1 = fmaf(h2, whn[1][2], fmaf(h1, whn[1][1], fmaf(h0, whn[1][0], bhn[1])));
            float hn2 = fmaf(h2, whn[2][2], fmaf(h1, whn[2][1], fmaf(h0, whn[2][0], bhn[2])));
            float i0 = fmaf(xv, win[0], bin_[0]);
            float i1 = fmaf(xv, win[1], bin_[1]);
            float i2 = fmaf(xv, win[2], bin_[2]);
            n0 = tanhx(fmaf(r0, hn0, i0));
            n1 = tanhx(fmaf(r1, hn1, i1));
            n2 = tanhx(fmaf(r2, hn2, i2));
        }
        float nh0 = fmaf(z0, h0 - n0, n0);
        float nh1 = fmaf(z1, h1 - n1, n1);
        float nh2 = fmaf(z2, h2 - n2, n2);
        bool act = t < len;
        h0 = act ? nh0 : h0;
        h1 = act ? nh1 : h1;
        h2 = act ? nh2 : h2;
    }

    // features = sigmoid(h_final)
    h0 = sig_h(0.5f * h0);
    h1 = sig_h(0.5f * h1);
    h2 = sig_h(0.5f * h2);

    // ---------------- decoder weights ----------------
    float vwi[6], vwh[6][3], vbs[6];
#pragma unroll
    for (int j = 0; j < 6; j++) {
        vwi[j] = 0.5f * dWih[j];
        vbs[j] = 0.5f * (dbih[j] + dbhh[j]);
#pragma unroll
        for (int k = 0; k < 3; k++) vwh[j][k] = 0.5f * dWhh[j * 3 + k];
    }
    float vwin[3], vbin[3], vwhn[3][3], vbhn[3];
#pragma unroll
    for (int j = 0; j < 3; j++) {
        vwin[j] = dWih[6 + j];
        vbin[j] = dbih[6 + j];
        vbhn[j] = dbhh[6 + j];
#pragma unroll
        for (int k = 0; k < 3; k++) vwhn[j][k] = dWhh[(6 + j) * 3 + k];
    }
    const float lw0 = linW[0], lw1 = linW[1], lw2 = linW[2], lb = linb[0];

    float inp = 0.f;
    float acc0 = 0.f, acc1 = 0.f;

    // ---------------- decoder loop ----------------
#pragma unroll 2
    for (int t = 0; t < TSZ; t++) {
        float a[6];
#pragma unroll
        for (int j = 0; j < 6; j++)
            a[j] = fmaf(h2, vwh[j][2], fmaf(h1, vwh[j][1], fmaf(h0, vwh[j][0], fmaf(inp, vwi[j], vbs[j]))));
        float r0 = sig_h(a[0]), r1 = sig_h(a[1]), r2 = sig_h(a[2]);
        float z0 = sig_h(a[3]), z1 = sig_h(a[4]), z2 = sig_h(a[5]);

        float hn0 = fmaf(h2, vwhn[0][2], fmaf(h1, vwhn[0][1], fmaf(h0, vwhn[0][0], vbhn[0])));
        float hn1 = fmaf(h2, vwhn[1][2], fmaf(h1, vwhn[1][1], fmaf(h0, vwhn[1][0], vbhn[1])));
        float hn2 = fmaf(h2, vwhn[2][2], fmaf(h1, vwhn[2][1], fmaf(h0, vwhn[2][0], vbhn[2])));
        float i0 = fmaf(inp, vwin[0], vbin[0]);
        float i1 = fmaf(inp, vwin[1], vbin[1]);
        float i2 = fmaf(inp, vwin[2], vbin[2]);
        float n0 = tanhx(fmaf(r0, hn0, i0));
        float n1 = tanhx(fmaf(r1, hn1, i1));
        float n2 = tanhx(fmaf(r2, hn2, i2));

        h0 = fmaf(z0, h0 - n0, n0);
        h1 = fmaf(z1, h1 - n1, n1);
        h2 = fmaf(z2, h2 - n2, n2);

        float outv = fmaf(h2, lw2, fmaf(h1, lw1, fmaf(h0, lw0, lb)));
        inp = outv;

        bool valid = t < len;
        float o  = valid ? outv : 0.f;
        g_oT[(long)t * BSZ + b] = o;
        float xv = g_xT[(long)t * BSZ + b];
        float xm = valid ? xv : 0.f;
        float d  = xm - o;
        if (t & 1) acc1 = fmaf(d, d, acc1); else acc0 = fmaf(d, d, acc0);
    }

    g_loss_partial[b] = (double)acc0 + (double)acc1;
}

// x[B][T] -> g_xT[T][B], tiled
__global__ void transpose_in(const float* __restrict__ src)
{
    __shared__ float tile[32][33];
    int tx = threadIdx.x, ty = threadIdx.y;
    int t0 = blockIdx.x * 32, b0 = blockIdx.y * 32;
#pragma unroll
    for (int i = ty; i < 32; i += 8)
        tile[i][tx] = src[(long)(b0 + i) * TSZ + t0 + tx];
    __syncthreads();
#pragma unroll
    for (int i = ty; i < 32; i += 8)
        g_xT[(long)(t0 + i) * BSZ + b0 + tx] = tile[tx][i];
}

// g_oT[T][B] -> output[B][T], tiled  (FIXED: swap indices on the write side)
__global__ void transpose_out(float* __restrict__ dst)
{
    __shared__ float tile[32][33];
    int tx = threadIdx.x, ty = threadIdx.y;
    int t0 = blockIdx.x * 32, b0 = blockIdx.y * 32;
#pragma unroll
    for (int i = ty; i < 32; i += 8)
        tile[i][tx] = g_oT[(long)(t0 + i) * BSZ + b0 + tx];   // tile[t][b]
    __syncthreads();
#pragma unroll
    for (int i = ty; i < 32; i += 8)
        dst[(long)(b0 + i) * TSZ + t0 + tx] = tile[tx][i];    // transposed read
}

// Coalesced elementwise x_pad
__global__ void xpad_kernel(const float* __restrict__ x, const int* __restrict__ lens,
                            float* __restrict__ xpad)
{
    int idx = blockIdx.x * blockDim.x + threadIdx.x;
    int t = idx & (TSZ - 1);
    int b = idx >> 12;
    float v = x[idx];
    xpad[idx] = (t < lens[b]) ? v : 0.f;
}

// Deterministic fixed-order reduction -> scalar loss
__global__ void loss_kernel(float* __restrict__ out_loss)
{
    __shared__ double s[1024];
    int tid = threadIdx.x;
    double a = 0.0;
    for (int i = tid; i < BSZ; i += 1024) a += g_loss_partial[i];
    s[tid] = a;
    __syncthreads();
    for (int off = 512; off > 0; off >>= 1) {
        if (tid < off) s[tid] += s[tid + off];
        __syncthreads();
    }
    if (tid == 0) out_loss[0] = (float)(s[0] / ((double)BSZ * (double)TSZ));
}

extern "C" void kernel_launch(void* const* d_in, const int* in_sizes, int n_in,
                              void* d_out, int out_size)
{
    const float* x    = (const float*)d_in[0];
    const int*   lens = (const int*)  d_in[1];
    const float* eWih = (const float*)d_in[2];
    const float* eWhh = (const float*)d_in[3];
    const float* ebih = (const float*)d_in[4];
    const float* ebhh = (const float*)d_in[5];
    const float* dWih = (const float*)d_in[6];
    const float* dWhh = (const float*)d_in[7];
    const float* dbih = (const float*)d_in[8];
    const float* dbhh = (const float*)d_in[9];
    const float* linW = (const float*)d_in[10];
    const float* linb = (const float*)d_in[11];

    float* out    = (float*)d_out;
    float* loss   = out;                       // [1]
    float* xpad   = out + 1;                   // [B*T]
    float* output = out + 1 + (long)BSZ * TSZ; // [B*T]

    dim3 tb(32, 8);
    dim3 tg(TSZ / 32, BSZ / 32);
    transpose_in<<<tg, tb>>>(x);
    gru_kernel<<<BSZ / 32, 32>>>(lens, eWih, eWhh, ebih, ebhh,
                                 dWih, dWhh, dbih, dbhh, linW, linb);
    transpose_out<<<tg, tb>>>(output);
    xpad_kernel<<<(BSZ * TSZ) / 256, 256>>>(x, lens, xpad);
    loss_kernel<<<1, 1024>>>(loss);
}

// round 4
// speedup vs baseline: 2.3668x; 2.3668x over previous
#include <cuda_runtime.h>

#define BSZ 4096
#define TSZ 4096
#define NTOT ((long)BSZ * TSZ)

#define FIN_BLOCKS 2048
#define FIN_THREADS 256

// raw (unmasked) decoder outputs, [B][T], 16B-aligned for vector stores
__device__ __align__(16) float g_o[NTOT];
// per-block loss partial sums from finalize kernel
__device__ double g_bsum[FIN_BLOCKS];

__device__ __forceinline__ float tanhx(float x) {
    float y; asm("tanh.approx.f32 %0, %1;" : "=f"(y) : "f"(x)); return y;
}
// sigmoid with pre-halved argument: sig(a) = 0.5*tanh(a/2)+0.5; caller passes a/2
__device__ __forceinline__ float sig_h(float ah) { return fmaf(0.5f, tanhx(ah), 0.5f); }

// One thread per batch element. Encoder (masked) then autoregressive decoder.
__global__ void __launch_bounds__(32, 1) gru_kernel(
    const float* __restrict__ x, const int* __restrict__ lens,
    const float* __restrict__ eWih, const float* __restrict__ eWhh,
    const float* __restrict__ ebih, const float* __restrict__ ebhh,
    const float* __restrict__ dWih, const float* __restrict__ dWhh,
    const float* __restrict__ dbih, const float* __restrict__ dbhh,
    const float* __restrict__ linW, const float* __restrict__ linb)
{
    const int b   = blockIdx.x * 32 + threadIdx.x;
    const int len = lens[b];
    const float* __restrict__ xrow = x + (long)b * TSZ;

    float h0 = 0.f, h1 = 0.f, h2 = 0.f;

    // ---------------- encoder weights (r,z rows pre-halved for sigmoid) --------
    {
        float wi[6], wh[6][3], bs[6];
#pragma unroll
        for (int j = 0; j < 6; j++) {
            wi[j] = 0.5f * eWih[j];
            bs[j] = 0.5f * (ebih[j] + ebhh[j]);
#pragma unroll
            for (int k = 0; k < 3; k++) wh[j][k] = 0.5f * eWhh[j * 3 + k];
        }
        float win[3], bin_[3], whn[3][3], bhn[3];
#pragma unroll
        for (int j = 0; j < 3; j++) {
            win[j]  = eWih[6 + j];
            bin_[j] = ebih[6 + j];
            bhn[j]  = ebhh[6 + j];
#pragma unroll
            for (int k = 0; k < 3; k++) whn[j][k] = eWhh[(6 + j) * 3 + k];
        }

        auto enc_step = [&](float xv, int t) {
            float a[6];
#pragma unroll
            for (int j = 0; j < 6; j++)
                a[j] = fmaf(h2, wh[j][2], fmaf(h1, wh[j][1], fmaf(h0, wh[j][0], fmaf(xv, wi[j], bs[j]))));
            float r0 = sig_h(a[0]), r1 = sig_h(a[1]), r2 = sig_h(a[2]);
            float z0 = sig_h(a[3]), z1 = sig_h(a[4]), z2 = sig_h(a[5]);

            float hn0 = fmaf(h2, whn[0][2], fmaf(h1, whn[0][1], fmaf(h0, whn[0][0], bhn[0])));
            float hn1 = fmaf(h2, whn[1][2], fmaf(h1, whn[1][1], fmaf(h0, whn[1][0], bhn[1])));
            float hn2 = fmaf(h2, whn[2][2], fmaf(h1, whn[2][1], fmaf(h0, whn[2][0], bhn[2])));
            float i0 = fmaf(xv, win[0], bin_[0]);
            float i1 = fmaf(xv, win[1], bin_[1]);
            float i2 = fmaf(xv, win[2], bin_[2]);
            float n0 = tanhx(fmaf(r0, hn0, i0));
            float n1 = tanhx(fmaf(r1, hn1, i1));
            float n2 = tanhx(fmaf(r2, hn2, i2));

            float nh0 = fmaf(z0, h0 - n0, n0);
            float nh1 = fmaf(z1, h1 - n1, n1);
            float nh2 = fmaf(z2, h2 - n2, n2);
            bool act = t < len;
            h0 = act ? nh0 : h0;
            h1 = act ? nh1 : h1;
            h2 = act ? nh2 : h2;
        };

        const int wmax  = __reduce_max_sync(0xFFFFFFFFu, len);
        const int wmax4 = (wmax + 3) & ~3;
        for (int t = 0; t < wmax4; t += 4) {
            const float4 xq = *(const float4*)(xrow + t);
            enc_step(xq.x, t + 0);
            enc_step(xq.y, t + 1);
            enc_step(xq.z, t + 2);
            enc_step(xq.w, t + 3);
        }
    }

    // features = sigmoid(h_final)
    h0 = sig_h(0.5f * h0);
    h1 = sig_h(0.5f * h1);
    h2 = sig_h(0.5f * h2);

    // ---------------- decoder ----------------
    float vwi[6], vwh[6][3], vbs[6];
#pragma unroll
    for (int j = 0; j < 6; j++) {
        vwi[j] = 0.5f * dWih[j];
        vbs[j] = 0.5f * (dbih[j] + dbhh[j]);
#pragma unroll
        for (int k = 0; k < 3; k++) vwh[j][k] = 0.5f * dWhh[j * 3 + k];
    }
    float vwin[3], vbin[3], vwhn[3][3], vbhn[3];
#pragma unroll
    for (int j = 0; j < 3; j++) {
        vwin[j] = dWih[6 + j];
        vbin[j] = dbih[6 + j];
        vbhn[j] = dbhh[6 + j];
#pragma unroll
        for (int k = 0; k < 3; k++) vwhn[j][k] = dWhh[(6 + j) * 3 + k];
    }
    const float lw0 = linW[0], lw1 = linW[1], lw2 = linW[2], lb = linb[0];

    float inp = 0.f;
    float* __restrict__ grow = g_o + (long)b * TSZ;

    auto dec_step = [&]() -> float {
        float a[6];
#pragma unroll
        for (int j = 0; j < 6; j++)
            a[j] = fmaf(h2, vwh[j][2], fmaf(h1, vwh[j][1], fmaf(h0, vwh[j][0], fmaf(inp, vwi[j], vbs[j]))));
        float r0 = sig_h(a[0]), r1 = sig_h(a[1]), r2 = sig_h(a[2]);
        float z0 = sig_h(a[3]), z1 = sig_h(a[4]), z2 = sig_h(a[5]);

        float hn0 = fmaf(h2, vwhn[0][2], fmaf(h1, vwhn[0][1], fmaf(h0, vwhn[0][0], vbhn[0])));
        float hn1 = fmaf(h2, vwhn[1][2], fmaf(h1, vwhn[1][1], fmaf(h0, vwhn[1][0], vbhn[1])));
        float hn2 = fmaf(h2, vwhn[2][2], fmaf(h1, vwhn[2][1], fmaf(h0, vwhn[2][0], vbhn[2])));
        float i0 = fmaf(inp, vwin[0], vbin[0]);
        float i1 = fmaf(inp, vwin[1], vbin[1]);
        float i2 = fmaf(inp, vwin[2], vbin[2]);
        float n0 = tanhx(fmaf(r0, hn0, i0));
        float n1 = tanhx(fmaf(r1, hn1, i1));
        float n2 = tanhx(fmaf(r2, hn2, i2));

        h0 = fmaf(z0, h0 - n0, n0);
        h1 = fmaf(z1, h1 - n1, n1);
        h2 = fmaf(z2, h2 - n2, n2);

        float outv = fmaf(h2, lw2, fmaf(h1, lw1, fmaf(h0, lw0, lb)));
        inp = outv;
        return outv;
    };

    for (int t = 0; t < TSZ; t += 4) {
        float o0 = dec_step();
        float o1 = dec_step();
        float o2 = dec_step();
        float o3 = dec_step();
        *(float4*)(grow + t) = make_float4(o0, o1, o2, o3);
    }
}

// Fused elementwise pass: xpad, masked output copy, loss partials.
__global__ void finalize_kernel(const float* __restrict__ x,
                                const int* __restrict__ lens,
                                float* __restrict__ xpad,
                                float* __restrict__ outmasked)
{
    __shared__ double s[FIN_THREADS];
    const int tid = threadIdx.x;
    float acc = 0.f;
    for (long idx = (long)blockIdx.x * FIN_THREADS + tid; idx < NTOT;
         idx += (long)FIN_BLOCKS * FIN_THREADS) {
        int b = (int)(idx >> 12);
        int t = (int)(idx & (TSZ - 1));
        bool v = t < lens[b];
        float xv = x[idx];
        float ov = g_o[idx];
        float xm = v ? xv : 0.f;
        float om = v ? ov : 0.f;
        xpad[idx]      = xm;
        outmasked[idx] = om;
        float d = xm - om;
        acc = fmaf(d, d, acc);
    }
    s[tid] = (double)acc;
    __syncthreads();
    for (int off = FIN_THREADS / 2; off > 0; off >>= 1) {
        if (tid < off) s[tid] += s[tid + off];
        __syncthreads();
    }
    if (tid == 0) g_bsum[blockIdx.x] = s[0];
}

// Deterministic fixed-order reduction of block partials -> scalar loss
__global__ void loss_kernel(float* __restrict__ out_loss)
{
    __shared__ double s[1024];
    int tid = threadIdx.x;
    double a = 0.0;
    for (int i = tid; i < FIN_BLOCKS; i += 1024) a += g_bsum[i];
    s[tid] = a;
    __syncthreads();
    for (int off = 512; off > 0; off >>= 1) {
        if (tid < off) s[tid] += s[tid + off];
        __syncthreads();
    }
    if (tid == 0) out_loss[0] = (float)(s[0] / ((double)BSZ * (double)TSZ));
}

extern "C" void kernel_launch(void* const* d_in, const int* in_sizes, int n_in,
                              void* d_out, int out_size)
{
    const float* x    = (const float*)d_in[0];
    const int*   lens = (const int*)  d_in[1];
    const float* eWih = (const float*)d_in[2];
    const float* eWhh = (const float*)d_in[3];
    const float* ebih = (const float*)d_in[4];
    const float* ebhh = (const float*)d_in[5];
    const float* dWih = (const float*)d_in[6];
    const float* dWhh = (const float*)d_in[7];
    const float* dbih = (const float*)d_in[8];
    const float* dbhh = (const float*)d_in[9];
    const float* linW = (const float*)d_in[10];
    const float* linb = (const float*)d_in[11];

    float* out    = (float*)d_out;
    float* loss   = out;                       // [1]
    float* xpad   = out + 1;                   // [B*T]
    float* output = out + 1 + NTOT;            // [B*T]

    gru_kernel<<<BSZ / 32, 32>>>(x, lens, eWih, eWhh, ebih, ebhh,
                                 dWih, dWhh, dbih, dbhh, linW, linb);
    finalize_kernel<<<FIN_BLOCKS, FIN_THREADS>>>(x, lens, xpad, output);
    loss_kernel<<<1, 1024>>>(loss);
}

// round 5
// speedup vs baseline: 2.3723x; 1.0023x over previous
#include <cuda_runtime.h>

#define BSZ 4096
#define TSZ 4096
#define NTOT ((long)BSZ * TSZ)

#define FIN_BLOCKS 2048
#define FIN_THREADS 256

// raw (unmasked) decoder outputs, [B][T], 16B-aligned for vector stores
__device__ __align__(16) float g_o[NTOT];
// per-block loss partial sums from finalize kernel
__device__ double g_bsum[FIN_BLOCKS];

typedef unsigned long long u64;

__device__ __forceinline__ float tanhx(float x) {
    float y; asm("tanh.approx.f32 %0, %1;" : "=f"(y) : "f"(x)); return y;
}
__device__ __forceinline__ u64 pk2(float lo, float hi) {
    u64 r; asm("mov.b64 %0, {%1, %2};" : "=l"(r) : "f"(lo), "f"(hi)); return r;
}
__device__ __forceinline__ void up2(u64 v, float& lo, float& hi) {
    asm("mov.b64 {%0, %1}, %2;" : "=f"(lo), "=f"(hi) : "l"(v));
}
// packed (a*b+c) on both f32 halves — single FFMA2-class op on the fma pipe
__device__ __forceinline__ u64 f2fma(u64 a, u64 b, u64 c) {
    u64 d; asm("fma.rn.f32x2 %0, %1, %2, %3;" : "=l"(d) : "l"(a), "l"(b), "l"(c)); return d;
}

// One thread per batch element; gate math packed pairwise into f32x2.
__global__ void __launch_bounds__(32, 1) gru_kernel(
    const float* __restrict__ x, const int* __restrict__ lens,
    const float* __restrict__ eWih, const float* __restrict__ eWhh,
    const float* __restrict__ ebih, const float* __restrict__ ebhh,
    const float* __restrict__ dWih, const float* __restrict__ dWhh,
    const float* __restrict__ dbih, const float* __restrict__ dbhh,
    const float* __restrict__ linW, const float* __restrict__ linb)
{
    const int b   = blockIdx.x * 32 + threadIdx.x;
    const int len = lens[b];
    const float* __restrict__ xrow = x + (long)b * TSZ;

    const u64 HALF2 = pk2(0.5f, 0.5f);
    const u64 NEG2  = pk2(-1.0f, -1.0f);

    float h0 = 0.f, h1 = 0.f, h2 = 0.f;
    float c0 = 0.f, c1 = 0.f, c2 = 0.f;   // captured h at t == len-1

    // ================= encoder =================
    {
        // r/z gates paired (r_k, z_k), pre-halved for sigmoid-via-tanh
        u64 WIrz[3], BSrz[3], WH0rz[3], WH1rz[3], WH2rz[3];
#pragma unroll
        for (int k = 0; k < 3; k++) {
            WIrz[k]  = pk2(0.5f * eWih[k],                 0.5f * eWih[3 + k]);
            BSrz[k]  = pk2(0.5f * (ebih[k] + ebhh[k]),     0.5f * (ebih[3 + k] + ebhh[3 + k]));
            WH0rz[k] = pk2(0.5f * eWhh[k * 3 + 0],         0.5f * eWhh[(3 + k) * 3 + 0]);
            WH1rz[k] = pk2(0.5f * eWhh[k * 3 + 1],         0.5f * eWhh[(3 + k) * 3 + 1]);
            WH2rz[k] = pk2(0.5f * eWhh[k * 3 + 2],         0.5f * eWhh[(3 + k) * 3 + 2]);
        }
        // n gates: (n0,n1) packed + n2 scalar
        const u64 WIN01 = pk2(eWih[6], eWih[7]);
        const u64 BIN01 = pk2(ebih[6], ebih[7]);
        const u64 BHN01 = pk2(ebhh[6], ebhh[7]);
        const u64 WHN0  = pk2(eWhh[18], eWhh[21]);
        const u64 WHN1  = pk2(eWhh[19], eWhh[22]);
        const u64 WHN2  = pk2(eWhh[20], eWhh[23]);
        const float win2 = eWih[8], bin2 = ebih[8], bhn2 = ebhh[8];
        const float whn20 = eWhh[24], whn21 = eWhh[25], whn22 = eWhh[26];
        const int len_m1 = len - 1;

        auto enc_step = [&](float xv, int t) {
            u64 xp  = pk2(xv, xv);
            u64 hh0 = pk2(h0, h0), hh1 = pk2(h1, h1), hh2 = pk2(h2, h2);
            u64 arz0 = f2fma(hh2, WH2rz[0], f2fma(hh1, WH1rz[0], f2fma(hh0, WH0rz[0], f2fma(xp, WIrz[0], BSrz[0]))));
            u64 arz1 = f2fma(hh2, WH2rz[1], f2fma(hh1, WH1rz[1], f2fma(hh0, WH0rz[1], f2fma(xp, WIrz[1], BSrz[1]))));
            u64 arz2 = f2fma(hh2, WH2rz[2], f2fma(hh1, WH1rz[2], f2fma(hh0, WH0rz[2], f2fma(xp, WIrz[2], BSrz[2]))));
            float ar0, az0, ar1, az1, ar2, az2;
            up2(arz0, ar0, az0); up2(arz1, ar1, az1); up2(arz2, ar2, az2);
            float tr0 = tanhx(ar0), tr1 = tanhx(ar1), tr2 = tanhx(ar2);
            float tz0 = tanhx(az0), tz1 = tanhx(az1), tz2 = tanhx(az2);
            u64 r01 = f2fma(pk2(tr0, tr1), HALF2, HALF2);
            u64 z01 = f2fma(pk2(tz0, tz1), HALF2, HALF2);
            float r2 = fmaf(tr2, 0.5f, 0.5f), z2 = fmaf(tz2, 0.5f, 0.5f);

            u64 hn01 = f2fma(hh2, WHN2, f2fma(hh1, WHN1, f2fma(hh0, WHN0, BHN01)));
            float hn2 = fmaf(h2, whn22, fmaf(h1, whn21, fmaf(h0, whn20, bhn2)));
            u64 i01 = f2fma(xp, WIN01, BIN01);
            float i2 = fmaf(xv, win2, bin2);

            u64 na01 = f2fma(r01, hn01, i01);
            float na0, na1; up2(na01, na0, na1);
            float n0 = tanhx(na0), n1 = tanhx(na1);
            float n2 = tanhx(fmaf(r2, hn2, i2));

            u64 n01p = pk2(n0, n1);
            u64 h01p = pk2(h0, h1);
            u64 hmn  = f2fma(n01p, NEG2, h01p);     // h - n
            u64 h01n = f2fma(z01, hmn, n01p);
            up2(h01n, h0, h1);
            h2 = fmaf(z2, h2 - n2, n2);

            // capture final hidden state off the critical chain
            if (t == len_m1) { c0 = h0; c1 = h1; c2 = h2; }
        };

        const int wmax  = __reduce_max_sync(0xFFFFFFFFu, len);
        const int wmax4 = (wmax + 3) & ~3;
        for (int t = 0; t < wmax4; t += 4) {
            const float4 xq = *(const float4*)(xrow + t);
            enc_step(xq.x, t + 0);
            enc_step(xq.y, t + 1);
            enc_step(xq.z, t + 2);
            enc_step(xq.w, t + 3);
        }
    }

    // features = sigmoid(captured h)
    h0 = fmaf(tanhx(0.5f * c0), 0.5f, 0.5f);
    h1 = fmaf(tanhx(0.5f * c1), 0.5f, 0.5f);
    h2 = fmaf(tanhx(0.5f * c2), 0.5f, 0.5f);

    // ================= decoder =================
    {
        u64 WIrz[3], BSrz[3], WH0rz[3], WH1rz[3], WH2rz[3];
#pragma unroll
        for (int k = 0; k < 3; k++) {
            WIrz[k]  = pk2(0.5f * dWih[k],                 0.5f * dWih[3 + k]);
            BSrz[k]  = pk2(0.5f * (dbih[k] + dbhh[k]),     0.5f * (dbih[3 + k] + dbhh[3 + k]));
            WH0rz[k] = pk2(0.5f * dWhh[k * 3 + 0],         0.5f * dWhh[(3 + k) * 3 + 0]);
            WH1rz[k] = pk2(0.5f * dWhh[k * 3 + 1],         0.5f * dWhh[(3 + k) * 3 + 1]);
            WH2rz[k] = pk2(0.5f * dWhh[k * 3 + 2],         0.5f * dWhh[(3 + k) * 3 + 2]);
        }
        const u64 WIN01 = pk2(dWih[6], dWih[7]);
        const u64 BIN01 = pk2(dbih[6], dbih[7]);
        const u64 BHN01 = pk2(dbhh[6], dbhh[7]);
        const u64 WHN0  = pk2(dWhh[18], dWhh[21]);
        const u64 WHN1  = pk2(dWhh[19], dWhh[22]);
        const u64 WHN2  = pk2(dWhh[20], dWhh[23]);
        const float win2 = dWih[8], bin2 = dbih[8], bhn2 = dbhh[8];
        const float whn20 = dWhh[24], whn21 = dWhh[25], whn22 = dWhh[26];
        const float lw0 = linW[0], lw1 = linW[1], lw2 = linW[2], lb = linb[0];

        float inp = 0.f;
        float* __restrict__ grow = g_o + (long)b * TSZ;

        auto dec_step = [&]() -> float {
            u64 xp  = pk2(inp, inp);
            u64 hh0 = pk2(h0, h0), hh1 = pk2(h1, h1), hh2 = pk2(h2, h2);
            u64 arz0 = f2fma(hh2, WH2rz[0], f2fma(hh1, WH1rz[0], f2fma(hh0, WH0rz[0], f2fma(xp, WIrz[0], BSrz[0]))));
            u64 arz1 = f2fma(hh2, WH2rz[1], f2fma(hh1, WH1rz[1], f2fma(hh0, WH0rz[1], f2fma(xp, WIrz[1], BSrz[1]))));
            u64 arz2 = f2fma(hh2, WH2rz[2], f2fma(hh1, WH1rz[2], f2fma(hh0, WH0rz[2], f2fma(xp, WIrz[2], BSrz[2]))));
            float ar0, az0, ar1, az1, ar2, az2;
            up2(arz0, ar0, az0); up2(arz1, ar1, az1); up2(arz2, ar2, az2);
            float tr0 = tanhx(ar0), tr1 = tanhx(ar1), tr2 = tanhx(ar2);
            float tz0 = tanhx(az0), tz1 = tanhx(az1), tz2 = tanhx(az2);
            u64 r01 = f2fma(pk2(tr0, tr1), HALF2, HALF2);
            u64 z01 = f2fma(pk2(tz0, tz1), HALF2, HALF2);
            float r2 = fmaf(tr2, 0.5f, 0.5f), z2 = fmaf(tz2, 0.5f, 0.5f);

            u64 hn01 = f2fma(hh2, WHN2, f2fma(hh1, WHN1, f2fma(hh0, WHN0, BHN01)));
            float hn2 = fmaf(h2, whn22, fmaf(h1, whn21, fmaf(h0, whn20, bhn2)));
            u64 i01 = f2fma(xp, WIN01, BIN01);
            float i2 = fmaf(inp, win2, bin2);

            u64 na01 = f2fma(r01, hn01, i01);
            float na0, na1; up2(na01, na0, na1);
            float n0 = tanhx(na0), n1 = tanhx(na1);
            float n2 = tanhx(fmaf(r2, hn2, i2));

            u64 n01p = pk2(n0, n1);
            u64 h01p = pk2(h0, h1);
            u64 hmn  = f2fma(n01p, NEG2, h01p);
            u64 h01n = f2fma(z01, hmn, n01p);
            up2(h01n, h0, h1);
            h2 = fmaf(z2, h2 - n2, n2);

            float outv = fmaf(h2, lw2, fmaf(h1, lw1, fmaf(h0, lw0, lb)));
            inp = outv;
            return outv;
        };

        for (int t = 0; t < TSZ; t += 4) {
            float o0 = dec_step();
            float o1 = dec_step();
            float o2 = dec_step();
            float o3 = dec_step();
            *(float4*)(grow + t) = make_float4(o0, o1, o2, o3);
        }
    }
}

// Fused elementwise pass: xpad, masked output copy, loss partials.
__global__ void finalize_kernel(const float* __restrict__ x,
                                const int* __restrict__ lens,
                                float* __restrict__ xpad,
                                float* __restrict__ outmasked)
{
    __shared__ double s[FIN_THREADS];
    const int tid = threadIdx.x;
    float acc = 0.f;
    for (long idx = (long)blockIdx.x * FIN_THREADS + tid; idx < NTOT;
         idx += (long)FIN_BLOCKS * FIN_THREADS) {
        int b = (int)(idx >> 12);
        int t = (int)(idx & (TSZ - 1));
        bool v = t < lens[b];
        float xv = x[idx];
        float ov = g_o[idx];
        float xm = v ? xv : 0.f;
        float om = v ? ov : 0.f;
        xpad[idx]      = xm;
        outmasked[idx] = om;
        float d = xm - om;
        acc = fmaf(d, d, acc);
    }
    s[tid] = (double)acc;
    __syncthreads();
    for (int off = FIN_THREADS / 2; off > 0; off >>= 1) {
        if (tid < off) s[tid] += s[tid + off];
        __syncthreads();
    }
    if (tid == 0) g_bsum[blockIdx.x] = s[0];
}

// Deterministic fixed-order reduction of block partials -> scalar loss
__global__ void loss_kernel(float* __restrict__ out_loss)
{
    __shared__ double s[1024];
    int tid = threadIdx.x;
    double a = 0.0;
    for (int i = tid; i < FIN_BLOCKS; i += 1024) a += g_bsum[i];
    s[tid] = a;
    __syncthreads();
    for (int off = 512; off > 0; off >>= 1) {
        if (tid < off) s[tid] += s[tid + off];
        __syncthreads();
    }
    if (tid == 0) out_loss[0] = (float)(s[0] / ((double)BSZ * (double)TSZ));
}

extern "C" void kernel_launch(void* const* d_in, const int* in_sizes, int n_in,
                              void* d_out, int out_size)
{
    const float* x    = (const float*)d_in[0];
    const int*   lens = (const int*)  d_in[1];
    const float* eWih = (const float*)d_in[2];
    const float* eWhh = (const float*)d_in[3];
    const float* ebih = (const float*)d_in[4];
    const float* ebhh = (const float*)d_in[5];
    const float* dWih = (const float*)d_in[6];
    const float* dWhh = (const float*)d_in[7];
    const float* dbih = (const float*)d_in[8];
    const float* dbhh = (const float*)d_in[9];
    const float* linW = (const float*)d_in[10];
    const float* linb = (const float*)d_in[11];

    float* out    = (float*)d_out;
    float* loss   = out;                       // [1]
    float* xpad   = out + 1;                   // [B*T]
    float* output = out + 1 + NTOT;            // [B*T]

    gru_kernel<<<BSZ / 32, 32>>>(x, lens, eWih, eWhh, ebih, ebhh,
                                 dWih, dWhh, dbih, dbhh, linW, linb);
    finalize_kernel<<<FIN_BLOCKS, FIN_THREADS>>>(x, lens, xpad, output);
    loss_kernel<<<1, 1024>>>(loss);
}